// round 5
// baseline (speedup 1.0000x reference)
#include <cuda_runtime.h>
#include <cstdint>

// Unpool (inverse of tf.nn.max_pool_with_argmax):
//   val  : [16, 64, 64, 128]  float32
//   mask : [16, 64, 64, 128]  int64 OR int32 (JAX x64-config dependent)
//   out  : [16, 128, 128, 128] float32
//
// Gather-tile + SMEM-staged bulk stores:
//   Each block owns pooled (b, h, w0..w0+15) x all 128 channels. Its output is
//   exactly rows 2h and 2h+1 over columns [2*w0, 2*w0+32) x C: two contiguous
//   16KB spans. Threads compute the unpooled values into two 16KB SMEM tiles
//   (conflict-free STS.128), then thread 0 drains each tile with one
//   cp.async.bulk.global.shared::cta — clean 16KB linear DRAM bursts instead
//   of 8.4M interleaved 512B STG granules (R2/R4 profiles pinned at 4.71TB/s
//   with nothing else saturated -> store-stream efficiency is the limiter).
//
// dtype probe: if mask is int32, reading word 0 as int64 fuses
// m[0] | (m[1]<<32); m[1] >= 1 always, so the fused value >= 2^32 >> TOT=2^25.
// One uniform broadcast load is decisive.

#define B_  16
#define H_  64
#define W_  64
#define C_  128
#define H2_ 128
#define W2_ 128

static constexpr int       PER_BATCH = H2_ * W2_ * C_;            // 2,097,152
static constexpr long long TOT       = (long long)B_ * PER_BATCH; // 33,554,432
static constexpr int       ROW2      = W2_ * C_;                  // 16,384

struct Loc { int l0, l1, l2, l3; };

__device__ __forceinline__ uint32_t smem_u32(const void* p) {
    uint32_t a;
    asm("{ .reg .u64 t; cvta.to.shared.u64 t, %1; cvt.u32.u64 %0, t; }"
        : "=r"(a) : "l"(p));
    return a;
}

// Compute the 2x2 window for one c4 group and write it into the two SMEM row
// tiles. p = float4 column index of slot (dh=*, dw=0) within the row tile.
__device__ __forceinline__ void emit_smem(const float4 v, const Loc m, int base,
                                          int p, float4* __restrict__ s0,
                                          float4* __restrict__ s1) {
    const int r0 = m.l0 -  base;
    const int r1 = m.l1 - (base + 1);
    const int r2 = m.l2 - (base + 2);
    const int r3 = m.l3 - (base + 3);

    float4 o00, o01, o10, o11;
    o00.x = (r0 == 0)         ? v.x : 0.0f;
    o00.y = (r1 == 0)         ? v.y : 0.0f;
    o00.z = (r2 == 0)         ? v.z : 0.0f;
    o00.w = (r3 == 0)         ? v.w : 0.0f;

    o01.x = (r0 == C_)        ? v.x : 0.0f;
    o01.y = (r1 == C_)        ? v.y : 0.0f;
    o01.z = (r2 == C_)        ? v.z : 0.0f;
    o01.w = (r3 == C_)        ? v.w : 0.0f;

    o10.x = (r0 == ROW2)      ? v.x : 0.0f;
    o10.y = (r1 == ROW2)      ? v.y : 0.0f;
    o10.z = (r2 == ROW2)      ? v.z : 0.0f;
    o10.w = (r3 == ROW2)      ? v.w : 0.0f;

    o11.x = (r0 == ROW2 + C_) ? v.x : 0.0f;
    o11.y = (r1 == ROW2 + C_) ? v.y : 0.0f;
    o11.z = (r2 == ROW2 + C_) ? v.z : 0.0f;
    o11.w = (r3 == ROW2 + C_) ? v.w : 0.0f;

    s0[p]      = o00;   // row 2h,   dw=0
    s0[p + 32] = o01;   // row 2h,   dw=1
    s1[p]      = o10;   // row 2h+1, dw=0
    s1[p + 32] = o11;   // row 2h+1, dw=1
}

__global__ void __launch_bounds__(256)
unpool_kernel(const float4* __restrict__ val4,
              const void*   __restrict__ mask,
              float*        __restrict__ out) {
    // Two 16KB row tiles: [32 output columns x 128 channels] as float4.
    __shared__ float4 s0[1024];
    __shared__ float4 s1[1024];

    const int tid = threadIdx.x;

    // Block tile decode: 512 consecutive c4-groups = (b, h, w0..w0+15).
    const int idx0 = blockIdx.x * 512;
    const int b    = idx0 >> 17;
    const int h    = (idx0 >> 11) & 63;
    const int w0   = (idx0 >> 5)  & 63;     // multiple of 16

    // dtype probe: uniform broadcast load.
    const long long probe = __ldg((const long long*)mask);
    const bool is_i64 = (probe >= 0) && (probe < TOT);

    const int idxA = idx0 + tid;
    const int idxB = idxA + 256;

    const float4 vA = val4[idxA];
    const float4 vB = val4[idxB];

    // Per-thread decode within tile.
    const int c4  = tid & 31;
    const int c   = c4 << 2;
    const int wlA = tid >> 5;               // 0..7   (w = w0 + wlA)
    const int wlB = wlA + 8;                // 8..15

    // Per-batch-local flat index of slot (0,0), channel c.
    const int rowbase = (2 * h) * ROW2;
    const int baseA = rowbase + 2 * (w0 + wlA) * C_ + c;
    const int baseB = rowbase + 2 * (w0 + wlB) * C_ + c;

    Loc mA, mB;
    if (is_i64) {
        const longlong2* m = (const longlong2*)mask;
        const longlong2 a0 = m[(size_t)idxA * 2];
        const longlong2 a1 = m[(size_t)idxA * 2 + 1];
        const longlong2 b0 = m[(size_t)idxB * 2];
        const longlong2 b1 = m[(size_t)idxB * 2 + 1];
        const long long off = (long long)b * PER_BATCH;
        mA = { (int)(a0.x - off), (int)(a0.y - off),
               (int)(a1.x - off), (int)(a1.y - off) };
        mB = { (int)(b0.x - off), (int)(b0.y - off),
               (int)(b1.x - off), (int)(b1.y - off) };
    } else {
        const int4 a = ((const int4*)mask)[idxA];
        const int4 d = ((const int4*)mask)[idxB];
        const int off = b * PER_BATCH;
        mA = { a.x - off, a.y - off, a.z - off, a.w - off };
        mB = { d.x - off, d.y - off, d.z - off, d.w - off };
    }

    // SMEM float4 column index for slot dw=0: (2*wl)*32 + c4.
    emit_smem(vA, mA, baseA, (wlA << 6) + c4, s0, s1);
    emit_smem(vB, mB, baseB, (wlB << 6) + c4, s0, s1);

    __syncthreads();

    if (tid == 0) {
        asm volatile("fence.proxy.async.shared::cta;" ::: "memory");
        float* g0 = out + (size_t)b * PER_BATCH + (size_t)(2 * h) * ROW2
                        + (size_t)(2 * w0) * C_;
        float* g1 = g0 + ROW2;
        const uint32_t a0 = smem_u32(s0);
        const uint32_t a1 = smem_u32(s1);
        asm volatile("cp.async.bulk.global.shared::cta.bulk_group [%0], [%1], %2;"
                     :: "l"(g0), "r"(a0), "n"(16384) : "memory");
        asm volatile("cp.async.bulk.global.shared::cta.bulk_group [%0], [%1], %2;"
                     :: "l"(g1), "r"(a1), "n"(16384) : "memory");
        asm volatile("cp.async.bulk.commit_group;" ::: "memory");
        asm volatile("cp.async.bulk.wait_group 0;" ::: "memory");
    }
}

extern "C" void kernel_launch(void* const* d_in, const int* in_sizes, int n_in,
                              void* d_out, int out_size) {
    const float4* val4 = (const float4*)d_in[0];
    const void*   mask = d_in[1];
    float*        out  = (float*)d_out;

    const int n_elems = B_ * H_ * W_ * (C_ / 4);   // 2,097,152 c4-groups
    unpool_kernel<<<n_elems / 512, 256>>>(val4, mask, out);
}